// round 4
// baseline (speedup 1.0000x reference)
#include <cuda_runtime.h>
#include <cuda_fp16.h>
#include <cstdint>

// ============================================================
// DST-II y[16384,1024], y_{m-1} = sum_n x_n sin(pi (n+.5) m /1024)
// Factor n = 32a+b:  sin(A+B) = sinA cosB + cosA sinB,
//   A = pi a m/32 (depends on r = m mod 64), B = pi(b+.5)m/1024.
// Stage1: P[b,r'] = sum_a x sin(pi a r'/32), Q[b,r'] = sum_a x cos(..)
//         for r' in [0,32]; r>32 handled by sign-fold into basis2.
// Stage2: y_m = sum_b P[b,r']*(sgn*cosB) + Q[b,r']*sinB.
// One fused kernel: 16 signals/CTA, both stages through smem.
// ============================================================

#define BATCH   16384
#define SIGS    16

// smem layout (bytes)
#define SM_X    0          // [s16][a32][b32] fp16, row pitch 80
#define SM_W    40960      // [f80][a32] fp16, row pitch 80
#define SM_PQ   47360      // [rp33][s16][q64] fp16, rp pitch 2064, s row 128B, XOR-chunk swizzle by s
#define SM_B2   115472     // 4 ring slots x 2 tiles x 4096 (tile: [n32][q64] fp16, XOR swizzle by n)
#define SM_Y    148240     // [s16][1024] fp32
#define SMEM_TOTAL 213776

// gmem scratch
__device__ __half g_W[80 * 32];          // [f][a], f = 2r'+pq (pq 0:sin->P,1:cos->Q), f>=66 zero
__device__ __half g_B2[34 * 2048];       // [rp][n32][q64], q = 2b+pq

// ---------------- helpers ----------------
__device__ __forceinline__ uint32_t smem_u32(const void* p) {
    uint32_t a;
    asm("{ .reg .u64 t; cvta.to.shared.u64 t, %1; cvt.u32.u64 %0, t; }" : "=r"(a) : "l"(p));
    return a;
}
__device__ __forceinline__ void cp_async16(uint32_t dst, const void* src) {
    asm volatile("cp.async.cg.shared.global [%0], [%1], 16;\n"
                 :: "r"(dst), "l"(__cvta_generic_to_global(src)) : "memory");
}
#define CP_COMMIT() asm volatile("cp.async.commit_group;\n" ::: "memory")
__device__ __forceinline__ void cp_wait(int n) {
    if (n == 0)      asm volatile("cp.async.wait_group 0;\n" ::: "memory");
    else if (n == 1) asm volatile("cp.async.wait_group 1;\n" ::: "memory");
    else if (n == 2) asm volatile("cp.async.wait_group 2;\n" ::: "memory");
    else             asm volatile("cp.async.wait_group 3;\n" ::: "memory");
}
__device__ __forceinline__ void ldm_x4(uint32_t* r, uint32_t addr) {
    asm volatile("ldmatrix.sync.aligned.m8n8.x4.shared.b16 {%0,%1,%2,%3}, [%4];\n"
                 : "=r"(r[0]), "=r"(r[1]), "=r"(r[2]), "=r"(r[3]) : "r"(addr));
}
__device__ __forceinline__ void ldm_x4_t(uint32_t* r, uint32_t addr) {
    asm volatile("ldmatrix.sync.aligned.m8n8.x4.trans.shared.b16 {%0,%1,%2,%3}, [%4];\n"
                 : "=r"(r[0]), "=r"(r[1]), "=r"(r[2]), "=r"(r[3]) : "r"(addr));
}
__device__ __forceinline__ void mma_16816(float* c, const uint32_t* a, const uint32_t* b) {
    asm volatile(
        "mma.sync.aligned.m16n8k16.row.col.f32.f16.f16.f32 "
        "{%0,%1,%2,%3}, {%4,%5,%6,%7}, {%8,%9}, {%0,%1,%2,%3};\n"
        : "+f"(c[0]), "+f"(c[1]), "+f"(c[2]), "+f"(c[3])
        : "r"(a[0]), "r"(a[1]), "r"(a[2]), "r"(a[3]), "r"(b[0]), "r"(b[1]));
}
__device__ __forceinline__ void sts16(uint32_t addr, __half v) {
    asm volatile("st.shared.b16 [%0], %1;\n" :: "r"(addr), "h"(*reinterpret_cast<uint16_t*>(&v)));
}
__device__ __forceinline__ void sts32f(uint32_t addr, float v) {
    asm volatile("st.shared.f32 [%0], %1;\n" :: "r"(addr), "f"(v));
}

// ============================================================
// Basis builders (exact integer angle reduction)
// ============================================================
__global__ void build_w_kernel() {
    for (int id = threadIdx.x; id < 80 * 32; id += blockDim.x) {
        int f = id >> 5, a = id & 31;
        int rp = f >> 1, pq = f & 1;
        float v = 0.0f;
        if (rp <= 32) {
            int mm = pq ? ((a * rp + 16) & 63) : ((a * rp) & 63);   // cos = sin(z + pi/2)
            v = sinpif((float)mm * (1.0f / 32.0f));
        }
        g_W[id] = __float2half_rn(v);
    }
}

__global__ void build_b2_kernel() {
    int rp = blockIdx.x;   // 0..32
    for (int id = threadIdx.x; id < 32 * 64; id += blockDim.x) {
        int col = id >> 6, q = id & 63;
        int b = q >> 1, pq = q & 1;
        float v = 0.0f;
        bool valid = !(col >= 16 && (rp == 0 || rp == 32));
        if (valid) {
            int m;
            float sgn = 1.0f;
            if (col < 16) m = (rp == 0) ? 64 * (col + 1) : (rp + 64 * col);
            else { m = (64 - rp) + 64 * (col - 16); sgn = -1.0f; }
            int ang = ((2 * b + 1) * m) & 4095;
            if (pq == 0) {   // multiplies P: sgn * cosB
                v = sgn * sinpif((float)((ang + 1024) & 4095) * (1.0f / 2048.0f));
            } else {         // multiplies Q: sinB
                v = sinpif((float)ang * (1.0f / 2048.0f));
            }
        }
        g_B2[rp * 2048 + id] = __float2half_rn(v);
    }
}

// ============================================================
// Main fused kernel: 16 signals per CTA, 256 threads.
// ============================================================
__global__ void __launch_bounds__(256, 1)
dst_fused_kernel(const float* __restrict__ x, float* __restrict__ y) {
    extern __shared__ char smem[];
    const uint32_t sb = smem_u32(smem);
    const int tid  = threadIdx.x;
    const int wid  = tid >> 5;
    const int lane = tid & 31;
    const int jj   = lane >> 3;
    const int ri   = lane & 7;
    const size_t s_base = (size_t)blockIdx.x * SIGS;

    // ---- B2 pair prefetch helper: pair p -> ring slot p&3 ----
    auto prefetch_pair = [&](int p) {
        #pragma unroll
        for (int rr = 0; rr < 2; rr++) {
            int id   = rr * 256 + tid;       // 512 chunks
            int tile = id >> 8;
            int n    = (id >> 3) & 31;
            int c    = id & 7;
            int rpp  = 2 * p + tile;         // may be 33 on last pair (g_B2 padded to 34)
            uint32_t dst = sb + SM_B2 + (uint32_t)((p & 3) * 8192 + tile * 4096
                         + n * 128 + ((c ^ (n & 7)) << 4));
            cp_async16(dst, (const char*)g_B2 + (size_t)rpp * 4096 + n * 128 + c * 16);
        }
        CP_COMMIT();
    };

    // ---- prologue: W (group0), B2 pairs 0,1,2 (groups 1..3) ----
    for (int id = tid; id < 320; id += 256) {
        int f = id >> 2, c = id & 3;
        cp_async16(sb + SM_W + (uint32_t)(f * 80 + c * 16),
                   (const char*)g_W + f * 64 + c * 16);
    }
    CP_COMMIT();
    prefetch_pair(0); prefetch_pair(1); prefetch_pair(2);

    // ---- load x (fp32) -> convert -> smem [s][a][b], row pitch 80B ----
    #pragma unroll
    for (int i = 0; i < 16; i++) {
        int s  = i;
        int n4 = tid;                       // 256 float4 per signal
        int n  = n4 * 4;
        int a  = n >> 5, b = n & 31;
        float4 v = *reinterpret_cast<const float4*>(x + (s_base + s) * 1024 + n);
        __half2 h0 = __floats2half2_rn(v.x, v.y);
        __half2 h1 = __floats2half2_rn(v.z, v.w);
        uint2 pk;
        pk.x = *reinterpret_cast<uint32_t*>(&h0);
        pk.y = *reinterpret_cast<uint32_t*>(&h1);
        *reinterpret_cast<uint2*>(smem + SM_X + s * 2560 + a * 80 + b * 2) = pk;
    }

    cp_wait(3);          // W resident (pairs 0..2 may pend)
    __syncthreads();

    // ================= Stage 1 =================
    // A = W [f80][a32] (non-trans), B = x [a][ (s,b) ] via ldmatrix.trans.
    // Warp w covers n = w*64 .. +63 (signals 2w, 2w+1).
    {
        uint32_t bf[2][8][2];
        #pragma unroll
        for (int ks = 0; ks < 2; ks++) {
            #pragma unroll
            for (int n16 = 0; n16 < 4; n16++) {
                int s    = 2 * wid + (n16 >> 1);
                int boff = (n16 & 1) * 16;
                int a    = ks * 16 + (lane & 15);
                uint32_t addr = sb + SM_X + (uint32_t)(s * 2560 + a * 80
                              + (boff + (lane >> 4) * 8) * 2);
                uint32_t t[4];
                ldm_x4_t(t, addr);
                bf[ks][n16 * 2 + 0][0] = t[0]; bf[ks][n16 * 2 + 0][1] = t[1];
                bf[ks][n16 * 2 + 1][0] = t[2]; bf[ks][n16 * 2 + 1][1] = t[3];
            }
        }
        #pragma unroll
        for (int mi = 0; mi < 5; mi++) {
            uint32_t af[2][4];
            #pragma unroll
            for (int ks = 0; ks < 2; ks++) {
                int f = mi * 16 + ((jj & 1) << 3) + ri;
                int c = ks * 2 + (jj >> 1);
                ldm_x4(af[ks], sb + SM_W + (uint32_t)(f * 80 + c * 16));
            }
            float acc[8][4];
            #pragma unroll
            for (int n8 = 0; n8 < 8; n8++)
                #pragma unroll
                for (int q = 0; q < 4; q++) acc[n8][q] = 0.0f;
            #pragma unroll
            for (int ks = 0; ks < 2; ks++)
                #pragma unroll
                for (int n8 = 0; n8 < 8; n8++)
                    mma_16816(acc[n8], af[ks], bf[ks][n8]);

            // scatter to PQ[rp][s][q], q = 2b+pq, fp16
            int g = lane >> 2, t4 = lane & 3;
            #pragma unroll
            for (int n8 = 0; n8 < 8; n8++) {
                int ncol = wid * 64 + n8 * 8 + 2 * t4;
                #pragma unroll
                for (int cc = 0; cc < 4; cc++) {
                    int f = mi * 16 + g + ((cc >> 1) << 3);
                    if (f < 66) {
                        int n = ncol + (cc & 1);
                        int rp = f >> 1, pq = f & 1;
                        int s = n >> 5, b = n & 31;
                        int u = (2 * b + pq) * 2;
                        uint32_t addr = sb + SM_PQ + (uint32_t)(rp * 2064 + s * 128
                                      + (((u >> 4) ^ (s & 7)) << 4) + (u & 15));
                        sts16(addr, __float2half_rn(acc[n8][cc]));
                    }
                }
            }
        }
    }
    __syncthreads();   // PQ complete

    // ================= Stage 2 =================
    // Per r' slot: y[s][m(col)] = PQ[rp][s16][q64] x B2[rp][n32][q64].
    // warp: half = wid>>2 picks slot in pair, n8j = wid&3 picks n8.
    const int half = wid >> 2;
    const int n8j  = wid & 3;
    const int g2   = lane >> 2;
    const int t2   = lane & 3;

    for (int it = 0; it <= 16; it++) {
        int pend = 16 - it; if (pend > 2) pend = 2;
        cp_wait(pend);
        __syncthreads();
        if (it + 3 <= 16) prefetch_pair(it + 3);

        int rp = 2 * it + half;
        if (rp <= 32) {
            uint32_t pqb = sb + SM_PQ + (uint32_t)(rp * 2064);
            uint32_t a2[4][4];
            #pragma unroll
            for (int ks = 0; ks < 4; ks++) {
                int s = ((jj & 1) << 3) + ri;
                int c = ks * 2 + (jj >> 1);
                ldm_x4(a2[ks], pqb + (uint32_t)(s * 128 + ((c ^ (s & 7)) << 4)));
            }
            uint32_t b2b = sb + SM_B2 + (uint32_t)((it & 3) * 8192 + half * 4096);
            uint32_t bt[2][4];
            #pragma unroll
            for (int q32 = 0; q32 < 2; q32++) {
                int n = n8j * 8 + (lane & 7);
                int c = q32 * 4 + (lane >> 3);
                ldm_x4(bt[q32], b2b + (uint32_t)(n * 128 + ((c ^ (n & 7)) << 4)));
            }
            float acc[4] = {0.f, 0.f, 0.f, 0.f};
            mma_16816(acc, a2[0], &bt[0][0]);
            mma_16816(acc, a2[1], &bt[0][2]);
            mma_16816(acc, a2[2], &bt[1][0]);
            mma_16816(acc, a2[3], &bt[1][2]);

            // scatter into y staging
            #pragma unroll
            for (int cc = 0; cc < 4; cc++) {
                int col = n8j * 8 + 2 * t2 + (cc & 1);
                int s   = g2 + ((cc >> 1) << 3);
                bool pad = (col >= 16) && (rp == 0 || rp == 32);
                if (!pad) {
                    int m = (col < 16) ? ((rp == 0) ? 64 * (col + 1) : (rp + 64 * col))
                                       : ((64 - rp) + 64 * (col - 16));
                    sts32f(sb + SM_Y + (uint32_t)(s * 4096 + (m - 1) * 4), acc[cc]);
                }
            }
        }
    }
    __syncthreads();

    // ---- coalesced copy-out ----
    #pragma unroll
    for (int i = 0; i < 16; i++) {
        int s  = i;
        int c4 = tid;   // 256 float4 per signal row
        float4 v = *reinterpret_cast<float4*>(smem + SM_Y + s * 4096 + c4 * 16);
        *reinterpret_cast<float4*>(y + (s_base + s) * 1024 + c4 * 4) = v;
    }
}

// ============================================================
// Launch
// ============================================================
extern "C" void kernel_launch(void* const* d_in, const int* in_sizes, int n_in,
                              void* d_out, int out_size) {
    const float* x = (const float*)d_in[0];
    float* y = (float*)d_out;

    build_w_kernel<<<1, 256>>>();
    build_b2_kernel<<<33, 256>>>();

    cudaFuncSetAttribute(dst_fused_kernel,
                         cudaFuncAttributeMaxDynamicSharedMemorySize, SMEM_TOTAL);
    dst_fused_kernel<<<BATCH / SIGS, 256, SMEM_TOTAL>>>(x, y);
}

// round 5
// speedup vs baseline: 1.1894x; 1.1894x over previous
#include <cuda_runtime.h>
#include <cuda_fp16.h>
#include <cstdint>

// ============================================================
// DST-II y[16384,1024] via Cooley-Tukey split n = 32a + b:
//  Stage1: P/Q[rp][b] = sum_a x[32a+b] * {sin,cos}(pi a rp/32), rp in [0,32]
//  Stage2: y_m = sum_b P*(sgn cosB) + Q*sinB,  B = pi(b+.5)m/1024
// Fused kernel, 16 signals/CTA, 512 threads, warp-owns-rp stage 2,
// stage-2 basis pre-packed in mma fragment layout (gmem->reg, no smem).
// ============================================================

#define BATCH   16384
#define SIGS    16
#define THREADS 512

// smem layout (bytes)
#define SM_X    0          // [s16][a32][b32] fp16, row pitch 80
#define SM_W    40960      // [f80][a32] fp16, row pitch 80 (dense 64B rows in gmem)
#define SM_PQ   47360      // [rp33]{[s16] rows of 128B, XOR-chunk swizzle}, pitch 2064
#define SM_Y    115472     // [s16][1024] fp32
#define SMEM_TOTAL 181008

// gmem scratch
__device__ __half g_W[80 * 32];      // [f][a], f = 2rp+pq (0:sin->P, 1:cos->Q)
__device__ uint2  g_B2f[33 * 512];   // [rp][nj4][ks4][lane32] -> {b0,b1} fp16x2 regs

// ---------------- helpers ----------------
__device__ __forceinline__ uint32_t smem_u32(const void* p) {
    uint32_t a;
    asm("{ .reg .u64 t; cvta.to.shared.u64 t, %1; cvt.u32.u64 %0, t; }" : "=r"(a) : "l"(p));
    return a;
}
__device__ __forceinline__ void cp_async16(uint32_t dst, const void* src) {
    asm volatile("cp.async.cg.shared.global [%0], [%1], 16;\n"
                 :: "r"(dst), "l"(__cvta_generic_to_global(src)) : "memory");
}
#define CP_COMMIT() asm volatile("cp.async.commit_group;\n" ::: "memory")
#define CP_WAIT0()  asm volatile("cp.async.wait_group 0;\n" ::: "memory")

__device__ __forceinline__ void ldm_x4(uint32_t* r, uint32_t addr) {
    asm volatile("ldmatrix.sync.aligned.m8n8.x4.shared.b16 {%0,%1,%2,%3}, [%4];\n"
                 : "=r"(r[0]), "=r"(r[1]), "=r"(r[2]), "=r"(r[3]) : "r"(addr));
}
__device__ __forceinline__ void ldm_x4_t(uint32_t* r, uint32_t addr) {
    asm volatile("ldmatrix.sync.aligned.m8n8.x4.trans.shared.b16 {%0,%1,%2,%3}, [%4];\n"
                 : "=r"(r[0]), "=r"(r[1]), "=r"(r[2]), "=r"(r[3]) : "r"(addr));
}
__device__ __forceinline__ void mma_16816(float* c, const uint32_t* a, const uint32_t* b) {
    asm volatile(
        "mma.sync.aligned.m16n8k16.row.col.f32.f16.f16.f32 "
        "{%0,%1,%2,%3}, {%4,%5,%6,%7}, {%8,%9}, {%0,%1,%2,%3};\n"
        : "+f"(c[0]), "+f"(c[1]), "+f"(c[2]), "+f"(c[3])
        : "r"(a[0]), "r"(a[1]), "r"(a[2]), "r"(a[3]), "r"(b[0]), "r"(b[1]));
}
__device__ __forceinline__ void sts16(uint32_t addr, __half v) {
    asm volatile("st.shared.b16 [%0], %1;\n" :: "r"(addr), "h"(*reinterpret_cast<uint16_t*>(&v)));
}
__device__ __forceinline__ void sts32f(uint32_t addr, float v) {
    asm volatile("st.shared.f32 [%0], %1;\n" :: "r"(addr), "f"(v));
}

// ============================================================
// Basis builder: block 0 -> W; blocks 1..33 -> B2f for rp = bid-1.
// Stage-2 basis element for (rp, col, q), q = 2b+pq:
//   col<16: m = (rp==0 ? 64(col+1) : rp+64col), sgn=+1
//   col>=16: m = (64-rp)+64(col-16), sgn=-1; invalid if rp==0||rp==32
//   pq==0 -> sgn*cos(pi(2b+1)m/2048) (multiplies P); pq==1 -> sin(..) (mult Q)
// ============================================================
__device__ __forceinline__ float b2_val(int rp, int col, int q) {
    if (col >= 16 && (rp == 0 || rp == 32)) return 0.0f;
    int m; float sgn = 1.0f;
    if (col < 16) m = (rp == 0) ? 64 * (col + 1) : (rp + 64 * col);
    else { m = (64 - rp) + 64 * (col - 16); sgn = -1.0f; }
    int b = q >> 1, pq = q & 1;
    int ang = ((2 * b + 1) * m) & 4095;
    if (pq == 0) return sgn * sinpif((float)((ang + 1024) & 4095) * (1.0f / 2048.0f));
    return sinpif((float)ang * (1.0f / 2048.0f));
}

__global__ void build_basis_kernel() {
    int bid = blockIdx.x;
    if (bid == 0) {
        for (int id = threadIdx.x; id < 80 * 32; id += blockDim.x) {
            int f = id >> 5, a = id & 31;
            int rp = f >> 1, pq = f & 1;
            float v = 0.0f;
            if (rp <= 32) {
                int mm = pq ? ((a * rp + 16) & 63) : ((a * rp) & 63);
                v = sinpif((float)mm * (1.0f / 32.0f));
            }
            g_W[id] = __float2half_rn(v);
        }
    } else {
        int rp = bid - 1;
        int tid = threadIdx.x;          // exactly 512 slots
        int nj = tid >> 7, ks = (tid >> 5) & 3, t = tid & 31;
        int col = nj * 8 + (t >> 2);
        int q0  = ks * 16 + 2 * (t & 3);
        __half2 r0 = __floats2half2_rn(b2_val(rp, col, q0),     b2_val(rp, col, q0 + 1));
        __half2 r1 = __floats2half2_rn(b2_val(rp, col, q0 + 8), b2_val(rp, col, q0 + 9));
        uint2 o;
        o.x = *reinterpret_cast<uint32_t*>(&r0);
        o.y = *reinterpret_cast<uint32_t*>(&r1);
        g_B2f[rp * 512 + (nj * 4 + ks) * 32 + t] = o;
    }
}

// ============================================================
// Stage-2 per-rp worker (per warp, no barriers):
// A = PQ[rp] (16s x 64q, smem ldmatrix), B = pre-packed frags (regs).
// ============================================================
__device__ __forceinline__ void stage2_rp(uint32_t sb, int rp, const uint2* B,
                                          int jj, int ri, int lane) {
    uint32_t pqb = sb + SM_PQ + (uint32_t)(rp * 2064);
    uint32_t a2[4][4];
    #pragma unroll
    for (int ks = 0; ks < 4; ks++) {
        int s = ((jj & 1) << 3) + ri;
        int c = ks * 2 + (jj >> 1);
        ldm_x4(a2[ks], pqb + (uint32_t)(s * 128 + ((c ^ (s & 7)) << 4)));
    }
    const int t4 = lane & 3, g2 = lane >> 2;
    #pragma unroll
    for (int nj = 0; nj < 4; nj++) {
        float acc[4] = {0.f, 0.f, 0.f, 0.f};
        #pragma unroll
        for (int ks = 0; ks < 4; ks++) {
            uint32_t breg[2] = { B[nj * 4 + ks].x, B[nj * 4 + ks].y };
            mma_16816(acc, a2[ks], breg);
        }
        #pragma unroll
        for (int cc = 0; cc < 4; cc++) {
            int col = nj * 8 + 2 * t4 + (cc & 1);
            int s   = g2 + ((cc >> 1) << 3);
            bool pad = (col >= 16) && (rp == 0 || rp == 32);
            if (!pad) {
                int m = (col < 16) ? ((rp == 0) ? 64 * (col + 1) : (rp + 64 * col))
                                   : ((64 - rp) + 64 * (col - 16));
                sts32f(sb + SM_Y + (uint32_t)(s * 4096 + (m - 1) * 4), acc[cc]);
            }
        }
    }
}

// ============================================================
// Main fused kernel: 16 signals / CTA, 512 threads (16 warps).
// ============================================================
__global__ void __launch_bounds__(THREADS, 1)
dst_fused_kernel(const float* __restrict__ x, float* __restrict__ y) {
    extern __shared__ char smem[];
    const uint32_t sb = smem_u32(smem);
    const int tid  = threadIdx.x;
    const int wid  = tid >> 5;
    const int lane = tid & 31;
    const int jj   = lane >> 3;
    const int ri   = lane & 7;
    const size_t s_base = (size_t)blockIdx.x * SIGS;

    // ---- W -> smem (dense 64B gmem rows -> 80B pitch) ----
    for (int id = tid; id < 320; id += THREADS) {
        int f = id >> 2, c = id & 3;
        cp_async16(sb + SM_W + (uint32_t)(f * 80 + c * 16),
                   (const char*)g_W + f * 64 + c * 16);
    }
    CP_COMMIT();

    // ---- x fp32 -> fp16 smem [s][a][b] pitch 80 ----
    #pragma unroll
    for (int i = 0; i < 8; i++) {
        int idx = i * THREADS + tid;            // 0..4095
        int s = idx >> 8;
        int n = (idx & 255) * 4;
        int a = n >> 5, b = n & 31;
        float4 v = *reinterpret_cast<const float4*>(x + (s_base + s) * 1024 + n);
        __half2 h0 = __floats2half2_rn(v.x, v.y);
        __half2 h1 = __floats2half2_rn(v.z, v.w);
        uint2 pk;
        pk.x = *reinterpret_cast<uint32_t*>(&h0);
        pk.y = *reinterpret_cast<uint32_t*>(&h1);
        *reinterpret_cast<uint2*>(smem + SM_X + s * 2560 + a * 80 + b * 2) = pk;
    }

    // ---- prefetch B fragments for this warp's first rp (independent of smem) ----
    const int rp0 = wid;
    uint2 B0[16];
    {
        const uint2* p = g_B2f + rp0 * 512 + lane;
        #pragma unroll
        for (int f = 0; f < 16; f++) B0[f] = __ldg(p + f * 32);
    }

    CP_WAIT0();
    __syncthreads();

    // ================= Stage 1: warp = one signal =================
    {
        uint32_t bf[2][4][2];
        #pragma unroll
        for (int ks = 0; ks < 2; ks++)
            #pragma unroll
            for (int n16 = 0; n16 < 2; n16++) {
                int a = ks * 16 + (lane & 15);
                uint32_t addr = sb + SM_X + (uint32_t)(wid * 2560 + a * 80
                              + (n16 * 16 + (lane >> 4) * 8) * 2);
                uint32_t t[4];
                ldm_x4_t(t, addr);
                bf[ks][n16 * 2 + 0][0] = t[0]; bf[ks][n16 * 2 + 0][1] = t[1];
                bf[ks][n16 * 2 + 1][0] = t[2]; bf[ks][n16 * 2 + 1][1] = t[3];
            }
        const int g = lane >> 2, t4 = lane & 3;
        #pragma unroll
        for (int mi = 0; mi < 5; mi++) {
            uint32_t af[2][4];
            #pragma unroll
            for (int ks = 0; ks < 2; ks++) {
                int f = mi * 16 + ((jj & 1) << 3) + ri;
                int c = ks * 2 + (jj >> 1);
                ldm_x4(af[ks], sb + SM_W + (uint32_t)(f * 80 + c * 16));
            }
            float acc[4][4];
            #pragma unroll
            for (int n8 = 0; n8 < 4; n8++)
                #pragma unroll
                for (int q = 0; q < 4; q++) acc[n8][q] = 0.0f;
            #pragma unroll
            for (int ks = 0; ks < 2; ks++)
                #pragma unroll
                for (int n8 = 0; n8 < 4; n8++)
                    mma_16816(acc[n8], af[ks], bf[ks][n8]);

            // scatter to PQ[rp][s=wid][q=2b+pq] fp16, swizzled rows
            #pragma unroll
            for (int n8 = 0; n8 < 4; n8++)
                #pragma unroll
                for (int cc = 0; cc < 4; cc++) {
                    int f = mi * 16 + g + ((cc >> 1) << 3);
                    if (f < 66) {
                        int b  = n8 * 8 + 2 * t4 + (cc & 1);
                        int rp = f >> 1, pq = f & 1;
                        int u  = (2 * b + pq) * 2;
                        uint32_t addr = sb + SM_PQ + (uint32_t)(rp * 2064 + wid * 128
                                      + (((u >> 4) ^ (wid & 7)) << 4) + (u & 15));
                        sts16(addr, __float2half_rn(acc[n8][cc]));
                    }
                }
        }
    }
    __syncthreads();   // PQ complete

    // ================= Stage 2: barrier-free, warp-owns-rp =================
    // prefetch second rp's B while first computes
    const int rp1 = 16 + wid;
    uint2 B1[16];
    {
        const uint2* p = g_B2f + rp1 * 512 + lane;
        #pragma unroll
        for (int f = 0; f < 16; f++) B1[f] = __ldg(p + f * 32);
    }

    stage2_rp(sb, rp0, B0, jj, ri, lane);
    stage2_rp(sb, rp1, B1, jj, ri, lane);

    if (wid == 0) {   // tail rp = 32
        uint2 B2[16];
        const uint2* p = g_B2f + 32 * 512 + lane;
        #pragma unroll
        for (int f = 0; f < 16; f++) B2[f] = __ldg(p + f * 32);
        stage2_rp(sb, 32, B2, jj, ri, lane);
    }

    __syncthreads();

    // ---- coalesced copy-out ----
    #pragma unroll
    for (int i = 0; i < 8; i++) {
        int idx = i * THREADS + tid;            // 0..4095 float4
        int s = idx >> 8, c4 = idx & 255;
        float4 v = *reinterpret_cast<float4*>(smem + SM_Y + s * 4096 + c4 * 16);
        *reinterpret_cast<float4*>(y + (s_base + s) * 1024 + c4 * 4) = v;
    }
}

// ============================================================
// Launch
// ============================================================
extern "C" void kernel_launch(void* const* d_in, const int* in_sizes, int n_in,
                              void* d_out, int out_size) {
    const float* x = (const float*)d_in[0];
    float* y = (float*)d_out;

    build_basis_kernel<<<34, 512>>>();

    cudaFuncSetAttribute(dst_fused_kernel,
                         cudaFuncAttributeMaxDynamicSharedMemorySize, SMEM_TOTAL);
    dst_fused_kernel<<<BATCH / SIGS, THREADS, SMEM_TOTAL>>>(x, y);
}

// round 6
// speedup vs baseline: 2.4635x; 2.0713x over previous
#include <cuda_runtime.h>
#include <cuda_fp16.h>
#include <cstdint>

// ============================================================
// DST-II y[16384,1024] via Cooley-Tukey split n = 32a + b:
//  Stage1: P/Q[rp][b] = sum_a x[32a+b] * {sin,cos}(pi a rp/32), rp in [0,32]
//  Stage2: y_m = sum_b P*(sgn cosB) + Q*sinB,  B = pi(b+.5)m/1024
// Fused kernel, 16 signals/CTA, 512 threads, warp-owns-rp stage 2.
// R6: conflict-free stage-1 scatter (q = pq*32+b, packed sts32),
//     4-way-max stage-2 scatter (per-s 32-word rotation),
//     y staging overlaid on dead x buffer.
// ============================================================

#define BATCH   16384
#define SIGS    16
#define THREADS 512

// smem layout (bytes)
#define SM_XY   0          // x: [s16][a32][b32] fp16 pitch 80 (40960 B), then y: [s16][1024] f32 (65536 B)
#define SM_W    65536      // [f80][a32] fp16, row pitch 80
#define SM_PQ   71936      // [rp33]{[s16] rows of 128B, XOR-chunk swizzle}, pitch 2064
#define SMEM_TOTAL 140048

// gmem scratch
__device__ __half g_W[80 * 32];      // [f][a], f = 2rp+pq (0:sin->P, 1:cos->Q)
__device__ uint2  g_B2f[33 * 512];   // [rp][nj4][ks4][lane32] -> {b0,b1} fp16x2 regs

// ---------------- helpers ----------------
__device__ __forceinline__ uint32_t smem_u32(const void* p) {
    uint32_t a;
    asm("{ .reg .u64 t; cvta.to.shared.u64 t, %1; cvt.u32.u64 %0, t; }" : "=r"(a) : "l"(p));
    return a;
}
__device__ __forceinline__ void cp_async16(uint32_t dst, const void* src) {
    asm volatile("cp.async.cg.shared.global [%0], [%1], 16;\n"
                 :: "r"(dst), "l"(__cvta_generic_to_global(src)) : "memory");
}
#define CP_COMMIT() asm volatile("cp.async.commit_group;\n" ::: "memory")
#define CP_WAIT0()  asm volatile("cp.async.wait_group 0;\n" ::: "memory")

__device__ __forceinline__ void ldm_x4(uint32_t* r, uint32_t addr) {
    asm volatile("ldmatrix.sync.aligned.m8n8.x4.shared.b16 {%0,%1,%2,%3}, [%4];\n"
                 : "=r"(r[0]), "=r"(r[1]), "=r"(r[2]), "=r"(r[3]) : "r"(addr));
}
__device__ __forceinline__ void ldm_x4_t(uint32_t* r, uint32_t addr) {
    asm volatile("ldmatrix.sync.aligned.m8n8.x4.trans.shared.b16 {%0,%1,%2,%3}, [%4];\n"
                 : "=r"(r[0]), "=r"(r[1]), "=r"(r[2]), "=r"(r[3]) : "r"(addr));
}
__device__ __forceinline__ void mma_16816(float* c, const uint32_t* a, const uint32_t* b) {
    asm volatile(
        "mma.sync.aligned.m16n8k16.row.col.f32.f16.f16.f32 "
        "{%0,%1,%2,%3}, {%4,%5,%6,%7}, {%8,%9}, {%0,%1,%2,%3};\n"
        : "+f"(c[0]), "+f"(c[1]), "+f"(c[2]), "+f"(c[3])
        : "r"(a[0]), "r"(a[1]), "r"(a[2]), "r"(a[3]), "r"(b[0]), "r"(b[1]));
}
__device__ __forceinline__ void sts32(uint32_t addr, uint32_t v) {
    asm volatile("st.shared.b32 [%0], %1;\n" :: "r"(addr), "r"(v));
}
__device__ __forceinline__ void sts32f(uint32_t addr, float v) {
    asm volatile("st.shared.f32 [%0], %1;\n" :: "r"(addr), "f"(v));
}

// ============================================================
// Basis builder. q-layout: q = pq*32 + b  (b = q&31, pq = q>>5).
//   col<16: m = (rp==0 ? 64(col+1) : rp+64col), sgn=+1
//   col>=16: m = (64-rp)+64(col-16), sgn=-1; invalid if rp==0||rp==32
//   pq==0 -> sgn*cos(pi(2b+1)m/2048); pq==1 -> sin(..)
// ============================================================
__device__ __forceinline__ float b2_val(int rp, int col, int q) {
    if (col >= 16 && (rp == 0 || rp == 32)) return 0.0f;
    int m; float sgn = 1.0f;
    if (col < 16) m = (rp == 0) ? 64 * (col + 1) : (rp + 64 * col);
    else { m = (64 - rp) + 64 * (col - 16); sgn = -1.0f; }
    int b = q & 31, pq = q >> 5;
    int ang = ((2 * b + 1) * m) & 4095;
    if (pq == 0) return sgn * sinpif((float)((ang + 1024) & 4095) * (1.0f / 2048.0f));
    return sinpif((float)ang * (1.0f / 2048.0f));
}

__global__ void build_basis_kernel() {
    int bid = blockIdx.x;
    if (bid == 0) {
        for (int id = threadIdx.x; id < 80 * 32; id += blockDim.x) {
            int f = id >> 5, a = id & 31;
            int rp = f >> 1, pq = f & 1;
            float v = 0.0f;
            if (rp <= 32) {
                int mm = pq ? ((a * rp + 16) & 63) : ((a * rp) & 63);
                v = sinpif((float)mm * (1.0f / 32.0f));
            }
            g_W[id] = __float2half_rn(v);
        }
    } else {
        int rp = bid - 1;
        int tid = threadIdx.x;          // exactly 512 slots
        int nj = tid >> 7, ks = (tid >> 5) & 3, t = tid & 31;
        int col = nj * 8 + (t >> 2);
        int q0  = ks * 16 + 2 * (t & 3);
        __half2 r0 = __floats2half2_rn(b2_val(rp, col, q0),     b2_val(rp, col, q0 + 1));
        __half2 r1 = __floats2half2_rn(b2_val(rp, col, q0 + 8), b2_val(rp, col, q0 + 9));
        uint2 o;
        o.x = *reinterpret_cast<uint32_t*>(&r0);
        o.y = *reinterpret_cast<uint32_t*>(&r1);
        g_B2f[rp * 512 + (nj * 4 + ks) * 32 + t] = o;
    }
}

// ============================================================
// Stage-2 per-rp worker (per warp, no barriers).
// y-staging store rotation: word = (M&~31)|((M+4s)&31), M = m-1.
// ============================================================
__device__ __forceinline__ void stage2_rp(uint32_t sb, int rp, const uint2* B,
                                          int jj, int ri, int lane) {
    uint32_t pqb = sb + SM_PQ + (uint32_t)(rp * 2064);
    uint32_t a2[4][4];
    #pragma unroll
    for (int ks = 0; ks < 4; ks++) {
        int s = ((jj & 1) << 3) + ri;
        int c = ks * 2 + (jj >> 1);
        ldm_x4(a2[ks], pqb + (uint32_t)(s * 128 + ((c ^ (s & 7)) << 4)));
    }
    const int t4 = lane & 3, g2 = lane >> 2;
    #pragma unroll
    for (int nj = 0; nj < 4; nj++) {
        float acc[4] = {0.f, 0.f, 0.f, 0.f};
        #pragma unroll
        for (int ks = 0; ks < 4; ks++) {
            uint32_t breg[2] = { B[nj * 4 + ks].x, B[nj * 4 + ks].y };
            mma_16816(acc, a2[ks], breg);
        }
        #pragma unroll
        for (int cc = 0; cc < 4; cc++) {
            int col = nj * 8 + 2 * t4 + (cc & 1);
            int s   = g2 + ((cc >> 1) << 3);
            bool pad = (col >= 16) && (rp == 0 || rp == 32);
            if (!pad) {
                int m = (col < 16) ? ((rp == 0) ? 64 * (col + 1) : (rp + 64 * col))
                                   : ((64 - rp) + 64 * (col - 16));
                uint32_t M = (uint32_t)(m - 1);
                uint32_t wrd = (M & ~31u) | ((M + 4u * (uint32_t)s) & 31u);
                sts32f(sb + SM_XY + (uint32_t)(s * 4096) + wrd * 4u, acc[cc]);
            }
        }
    }
}

// ============================================================
// Main fused kernel: 16 signals / CTA, 512 threads (16 warps).
// ============================================================
__global__ void __launch_bounds__(THREADS, 1)
dst_fused_kernel(const float* __restrict__ x, float* __restrict__ y) {
    extern __shared__ char smem[];
    const uint32_t sb = smem_u32(smem);
    const int tid  = threadIdx.x;
    const int wid  = tid >> 5;
    const int lane = tid & 31;
    const int jj   = lane >> 3;
    const int ri   = lane & 7;
    const size_t s_base = (size_t)blockIdx.x * SIGS;

    // ---- W -> smem (dense 64B gmem rows -> 80B pitch) ----
    for (int id = tid; id < 320; id += THREADS) {
        int f = id >> 2, c = id & 3;
        cp_async16(sb + SM_W + (uint32_t)(f * 80 + c * 16),
                   (const char*)g_W + f * 64 + c * 16);
    }
    CP_COMMIT();

    // ---- x fp32 -> fp16 smem [s][a][b] pitch 80 ----
    #pragma unroll
    for (int i = 0; i < 8; i++) {
        int idx = i * THREADS + tid;            // 0..4095
        int s = idx >> 8;
        int n = (idx & 255) * 4;
        int a = n >> 5, b = n & 31;
        float4 v = *reinterpret_cast<const float4*>(x + (s_base + s) * 1024 + n);
        __half2 h0 = __floats2half2_rn(v.x, v.y);
        __half2 h1 = __floats2half2_rn(v.z, v.w);
        uint2 pk;
        pk.x = *reinterpret_cast<uint32_t*>(&h0);
        pk.y = *reinterpret_cast<uint32_t*>(&h1);
        *reinterpret_cast<uint2*>(smem + SM_XY + s * 2560 + a * 80 + b * 2) = pk;
    }

    // ---- prefetch B fragments for first rp (independent of smem) ----
    const int rp0 = wid;
    uint2 B0[16];
    {
        const uint2* p = g_B2f + rp0 * 512 + lane;
        #pragma unroll
        for (int f = 0; f < 16; f++) B0[f] = __ldg(p + f * 32);
    }

    CP_WAIT0();
    __syncthreads();

    // ================= Stage 1: warp = one signal =================
    {
        uint32_t bf[2][4][2];
        #pragma unroll
        for (int ks = 0; ks < 2; ks++)
            #pragma unroll
            for (int n16 = 0; n16 < 2; n16++) {
                int a = ks * 16 + (lane & 15);
                uint32_t addr = sb + SM_XY + (uint32_t)(wid * 2560 + a * 80
                              + (n16 * 16 + (lane >> 4) * 8) * 2);
                uint32_t t[4];
                ldm_x4_t(t, addr);
                bf[ks][n16 * 2 + 0][0] = t[0]; bf[ks][n16 * 2 + 0][1] = t[1];
                bf[ks][n16 * 2 + 1][0] = t[2]; bf[ks][n16 * 2 + 1][1] = t[3];
            }
        const int g = lane >> 2, t4 = lane & 3;
        #pragma unroll
        for (int mi = 0; mi < 5; mi++) {
            uint32_t af[2][4];
            #pragma unroll
            for (int ks = 0; ks < 2; ks++) {
                int f = mi * 16 + ((jj & 1) << 3) + ri;
                int c = ks * 2 + (jj >> 1);
                ldm_x4(af[ks], sb + SM_W + (uint32_t)(f * 80 + c * 16));
            }
            float acc[4][4];
            #pragma unroll
            for (int n8 = 0; n8 < 4; n8++)
                #pragma unroll
                for (int q = 0; q < 4; q++) acc[n8][q] = 0.0f;
            #pragma unroll
            for (int ks = 0; ks < 2; ks++)
                #pragma unroll
                for (int n8 = 0; n8 < 4; n8++)
                    mma_16816(acc[n8], af[ks], bf[ks][n8]);

            // packed conflict-free scatter to PQ[rp][s=wid][q = pq*32 + b]
            #pragma unroll
            for (int n8 = 0; n8 < 4; n8++)
                #pragma unroll
                for (int ch = 0; ch < 2; ch++) {
                    int f = mi * 16 + g + (ch << 3);
                    if (f < 66) {
                        int b  = n8 * 8 + 2 * t4;        // even
                        int rp = f >> 1, pq = f & 1;
                        int u  = pq * 64 + 2 * b;        // byte offset, 4-aligned
                        __half2 h = __floats2half2_rn(acc[n8][2 * ch], acc[n8][2 * ch + 1]);
                        uint32_t addr = sb + SM_PQ + (uint32_t)(rp * 2064 + wid * 128
                                      + (((u >> 4) ^ (wid & 7)) << 4) + (u & 15));
                        sts32(addr, *reinterpret_cast<uint32_t*>(&h));
                    }
                }
        }
    }
    __syncthreads();   // PQ complete; x buffer now dead -> reused as y staging

    // ================= Stage 2: barrier-free, warp-owns-rp =================
    const int rp1 = 16 + wid;
    uint2 B1[16];
    {
        const uint2* p = g_B2f + rp1 * 512 + lane;
        #pragma unroll
        for (int f = 0; f < 16; f++) B1[f] = __ldg(p + f * 32);
    }

    stage2_rp(sb, rp0, B0, jj, ri, lane);
    stage2_rp(sb, rp1, B1, jj, ri, lane);

    if (wid == 0) {   // tail rp = 32
        uint2 B2[16];
        const uint2* p = g_B2f + 32 * 512 + lane;
        #pragma unroll
        for (int f = 0; f < 16; f++) B2[f] = __ldg(p + f * 32);
        stage2_rp(sb, 32, B2, jj, ri, lane);
    }

    __syncthreads();

    // ---- coalesced copy-out (inverts per-s 32-word rotation; rot = 4s, 4-aligned) ----
    #pragma unroll
    for (int i = 0; i < 8; i++) {
        int idx = i * THREADS + tid;            // 0..4095 float4
        int s = idx >> 8, c4 = idx & 255;
        uint32_t M = (uint32_t)(c4 * 4);
        uint32_t wrd = (M & ~31u) | ((M + 4u * (uint32_t)s) & 31u);
        float4 v = *reinterpret_cast<float4*>(smem + SM_XY + s * 4096 + wrd * 4);
        *reinterpret_cast<float4*>(y + (s_base + s) * 1024 + M) = v;
    }
}

// ============================================================
// Launch
// ============================================================
extern "C" void kernel_launch(void* const* d_in, const int* in_sizes, int n_in,
                              void* d_out, int out_size) {
    const float* x = (const float*)d_in[0];
    float* y = (float*)d_out;

    build_basis_kernel<<<34, 512>>>();

    cudaFuncSetAttribute(dst_fused_kernel,
                         cudaFuncAttributeMaxDynamicSharedMemorySize, SMEM_TOTAL);
    dst_fused_kernel<<<BATCH / SIGS, THREADS, SMEM_TOTAL>>>(x, y);
}

// round 7
// speedup vs baseline: 2.6814x; 1.0885x over previous
#include <cuda_runtime.h>
#include <cuda_fp16.h>
#include <cstdint>

// ============================================================
// DST-II y[16384,1024] via Cooley-Tukey split n = 32a + b:
//  Stage1: P/Q[rp][b] = sum_a x[32a+b] * {sin,cos}(pi a rp/32), rp in [0,32]
//  Stage2: y_m = sum_b P*(sgn cosB) + Q*sinB,  B = pi(b+.5)m/1024
// R7: 256 thr / 16 signals / CTA, 109KB smem -> 2 CTAs/SM.
//  - W basis as pre-packed mma A-fragments in gmem (ldg, L2-hot)
//  - B2 basis as pre-packed mma B-fragments (uint4 ldg, L2-hot)
//  - y staging fp16 overlaid on dead x buffer
//  - stage-2 scatter rotation rot = 4s + ((M>>7)&3): <=2-way conflicts
// ============================================================

#define BATCH   16384
#define SIGS    16
#define THREADS 256

// smem layout (bytes)
#define SM_XY   0          // x: [s16][a32][b32] fp16 pitch 80 = 40960 B; later y: [s16][1024] fp16 = 32768 B
#define SM_PQ   40960      // [rp33]{[s16] rows of 128B, XOR-chunk swizzle}, pitch 2064 = 68112 B
#define SMEM_TOTAL 109072

// gmem scratch (pre-packed mma fragments)
__device__ uint4 g_Wf[5 * 2 * 32];    // [mi5][ks2][lane32] A-fragments of W
__device__ uint4 g_B2f4[33 * 8 * 32]; // [rp][f2=nj*2+ksh][lane32] B-fragments (2 ks per uint4)

// ---------------- helpers ----------------
__device__ __forceinline__ uint32_t smem_u32(const void* p) {
    uint32_t a;
    asm("{ .reg .u64 t; cvta.to.shared.u64 t, %1; cvt.u32.u64 %0, t; }" : "=r"(a) : "l"(p));
    return a;
}
__device__ __forceinline__ void ldm_x4(uint32_t* r, uint32_t addr) {
    asm volatile("ldmatrix.sync.aligned.m8n8.x4.shared.b16 {%0,%1,%2,%3}, [%4];\n"
                 : "=r"(r[0]), "=r"(r[1]), "=r"(r[2]), "=r"(r[3]) : "r"(addr));
}
__device__ __forceinline__ void ldm_x4_t(uint32_t* r, uint32_t addr) {
    asm volatile("ldmatrix.sync.aligned.m8n8.x4.trans.shared.b16 {%0,%1,%2,%3}, [%4];\n"
                 : "=r"(r[0]), "=r"(r[1]), "=r"(r[2]), "=r"(r[3]) : "r"(addr));
}
__device__ __forceinline__ void mma_16816(float* c, const uint32_t* a, const uint32_t* b) {
    asm volatile(
        "mma.sync.aligned.m16n8k16.row.col.f32.f16.f16.f32 "
        "{%0,%1,%2,%3}, {%4,%5,%6,%7}, {%8,%9}, {%0,%1,%2,%3};\n"
        : "+f"(c[0]), "+f"(c[1]), "+f"(c[2]), "+f"(c[3])
        : "r"(a[0]), "r"(a[1]), "r"(a[2]), "r"(a[3]), "r"(b[0]), "r"(b[1]));
}
__device__ __forceinline__ void sts32(uint32_t addr, uint32_t v) {
    asm volatile("st.shared.b32 [%0], %1;\n" :: "r"(addr), "r"(v));
}
__device__ __forceinline__ void sts16(uint32_t addr, __half v) {
    asm volatile("st.shared.b16 [%0], %1;\n" :: "r"(addr), "h"(*reinterpret_cast<uint16_t*>(&v)));
}
__device__ __forceinline__ __half lds16(uint32_t addr) {
    uint16_t v;
    asm volatile("ld.shared.b16 %0, [%1];\n" : "=h"(v) : "r"(addr));
    return *reinterpret_cast<__half*>(&v);
}
__device__ __forceinline__ uint32_t pk2(float a, float b) {
    __half2 h = __floats2half2_rn(a, b);
    return *reinterpret_cast<uint32_t*>(&h);
}

// ============================================================
// Basis values
// ============================================================
__device__ __forceinline__ float w_val(int f, int a) {  // f = 2rp+pq
    int rp = f >> 1, pq = f & 1;
    if (rp > 32) return 0.0f;
    int mm = pq ? ((a * rp + 16) & 63) : ((a * rp) & 63);
    return sinpif((float)mm * (1.0f / 32.0f));
}
__device__ __forceinline__ float b2_val(int rp, int col, int q) {  // q = pq*32 + b
    if (col >= 16 && (rp == 0 || rp == 32)) return 0.0f;
    int m; float sgn = 1.0f;
    if (col < 16) m = (rp == 0) ? 64 * (col + 1) : (rp + 64 * col);
    else { m = (64 - rp) + 64 * (col - 16); sgn = -1.0f; }
    int b = q & 31, pq = q >> 5;
    int ang = ((2 * b + 1) * m) & 4095;
    if (pq == 0) return sgn * sinpif((float)((ang + 1024) & 4095) * (1.0f / 2048.0f));
    return sinpif((float)ang * (1.0f / 2048.0f));
}

__global__ void build_basis_kernel() {
    int bid = blockIdx.x;
    int tid = threadIdx.x;
    if (bid == 0) {
        // W A-fragments: [mi][ks][lane] -> quadrants a0..a3
        if (tid < 320) {
            int mi = tid >> 6, ks = (tid >> 5) & 1, l = tid & 31;
            int r0 = l >> 2, k0 = 16 * ks + 2 * (l & 3);
            uint4 o;
            o.x = pk2(w_val(mi * 16 + r0,     k0),     w_val(mi * 16 + r0,     k0 + 1));
            o.y = pk2(w_val(mi * 16 + 8 + r0, k0),     w_val(mi * 16 + 8 + r0, k0 + 1));
            o.z = pk2(w_val(mi * 16 + r0,     k0 + 8), w_val(mi * 16 + r0,     k0 + 9));
            o.w = pk2(w_val(mi * 16 + 8 + r0, k0 + 8), w_val(mi * 16 + 8 + r0, k0 + 9));
            g_Wf[(mi * 2 + ks) * 32 + l] = o;
        }
    } else {
        int rp = bid - 1;
        if (tid < 256) {
            int f2 = tid >> 5, t = tid & 31;
            int nj = f2 >> 1, ksh = f2 & 1;
            int col = nj * 8 + (t >> 2);
            int q0 = (2 * ksh) * 16 + 2 * (t & 3);
            int q1 = (2 * ksh + 1) * 16 + 2 * (t & 3);
            uint4 o;
            o.x = pk2(b2_val(rp, col, q0),     b2_val(rp, col, q0 + 1));
            o.y = pk2(b2_val(rp, col, q0 + 8), b2_val(rp, col, q0 + 9));
            o.z = pk2(b2_val(rp, col, q1),     b2_val(rp, col, q1 + 1));
            o.w = pk2(b2_val(rp, col, q1 + 8), b2_val(rp, col, q1 + 9));
            g_B2f4[rp * 256 + f2 * 32 + t] = o;
        }
    }
}

// ============================================================
// Stage-2 per-rp worker (per warp, no barriers).
// fp16 y staging; rot = 4s + ((M>>7)&3) (=t4, recoverable at copy-out).
// ============================================================
__device__ __forceinline__ void stage2_rp(uint32_t sb, int rp, const uint4* B,
                                          int jj, int ri, int lane) {
    uint32_t pqb = sb + SM_PQ + (uint32_t)(rp * 2064);
    uint32_t a2[4][4];
    #pragma unroll
    for (int ks = 0; ks < 4; ks++) {
        int s = ((jj & 1) << 3) + ri;
        int c = ks * 2 + (jj >> 1);
        ldm_x4(a2[ks], pqb + (uint32_t)(s * 128 + ((c ^ (s & 7)) << 4)));
    }
    const int t4 = lane & 3, g2 = lane >> 2;
    #pragma unroll
    for (int nj = 0; nj < 4; nj++) {
        float acc[4] = {0.f, 0.f, 0.f, 0.f};
        {
            uint32_t b0[2] = { B[nj * 2 + 0].x, B[nj * 2 + 0].y };
            mma_16816(acc, a2[0], b0);
            uint32_t b1[2] = { B[nj * 2 + 0].z, B[nj * 2 + 0].w };
            mma_16816(acc, a2[1], b1);
            uint32_t b2[2] = { B[nj * 2 + 1].x, B[nj * 2 + 1].y };
            mma_16816(acc, a2[2], b2);
            uint32_t b3[2] = { B[nj * 2 + 1].z, B[nj * 2 + 1].w };
            mma_16816(acc, a2[3], b3);
        }
        #pragma unroll
        for (int cc = 0; cc < 4; cc++) {
            int col = nj * 8 + 2 * t4 + (cc & 1);
            int s   = g2 + ((cc >> 1) << 3);
            bool pad = (col >= 16) && (rp == 0 || rp == 32);
            if (!pad) {
                int m = (col < 16) ? ((rp == 0) ? 64 * (col + 1) : (rp + 64 * col))
                                   : ((64 - rp) + 64 * (col - 16));
                uint32_t M = (uint32_t)(m - 1);
                uint32_t rot = 4u * (uint32_t)s + ((M >> 7) & 3u);
                uint32_t w = (M & ~31u) | ((M + rot) & 31u);
                sts16(sb + SM_XY + (uint32_t)(s * 2048) + 2u * w, __float2half_rn(acc[cc]));
            }
        }
    }
}

// ============================================================
// Main fused kernel: 16 signals / CTA, 256 threads (8 warps), 2 CTAs/SM.
// ============================================================
__global__ void __launch_bounds__(THREADS, 2)
dst_fused_kernel(const float* __restrict__ x, float* __restrict__ y) {
    extern __shared__ char smem[];
    const uint32_t sb = smem_u32(smem);
    const int tid  = threadIdx.x;
    const int wid  = tid >> 5;
    const int lane = tid & 31;
    const int jj   = lane >> 3;
    const int ri   = lane & 7;
    const size_t s_base = (size_t)blockIdx.x * SIGS;

    // ---- x fp32 -> fp16 smem [s][a][b] pitch 80 ----
    #pragma unroll
    for (int i = 0; i < 16; i++) {
        int idx = i * THREADS + tid;            // 0..4095
        int s = idx >> 8;
        int n = (idx & 255) * 4;
        int a = n >> 5, b = n & 31;
        float4 v = *reinterpret_cast<const float4*>(x + (s_base + s) * 1024 + n);
        uint2 pk;
        pk.x = pk2(v.x, v.y);
        pk.y = pk2(v.z, v.w);
        *reinterpret_cast<uint2*>(smem + SM_XY + s * 2560 + a * 80 + b * 2) = pk;
    }

    // ---- W A-fragments -> regs (L2-hot ldg) ----
    uint4 Wf[10];
    {
        const uint4* p = g_Wf + lane;
        #pragma unroll
        for (int f = 0; f < 10; f++) Wf[f] = __ldg(p + f * 32);
    }

    __syncthreads();

    // ================= Stage 1: warp = 2 signals =================
    const int g = lane >> 2, t4 = lane & 3;
    #pragma unroll
    for (int ss = 0; ss < 2; ss++) {
        const int s = wid * 2 + ss;
        uint32_t bf[2][4][2];
        #pragma unroll
        for (int ks = 0; ks < 2; ks++)
            #pragma unroll
            for (int n16 = 0; n16 < 2; n16++) {
                int a = ks * 16 + (lane & 15);
                uint32_t addr = sb + SM_XY + (uint32_t)(s * 2560 + a * 80
                              + (n16 * 16 + (lane >> 4) * 8) * 2);
                uint32_t t[4];
                ldm_x4_t(t, addr);
                bf[ks][n16 * 2 + 0][0] = t[0]; bf[ks][n16 * 2 + 0][1] = t[1];
                bf[ks][n16 * 2 + 1][0] = t[2]; bf[ks][n16 * 2 + 1][1] = t[3];
            }
        #pragma unroll
        for (int mi = 0; mi < 5; mi++) {
            float acc[4][4];
            #pragma unroll
            for (int n8 = 0; n8 < 4; n8++)
                #pragma unroll
                for (int q = 0; q < 4; q++) acc[n8][q] = 0.0f;
            #pragma unroll
            for (int ks = 0; ks < 2; ks++) {
                uint32_t af[4] = { Wf[mi * 2 + ks].x, Wf[mi * 2 + ks].y,
                                   Wf[mi * 2 + ks].z, Wf[mi * 2 + ks].w };
                #pragma unroll
                for (int n8 = 0; n8 < 4; n8++)
                    mma_16816(acc[n8], af, bf[ks][n8]);
            }
            // packed conflict-free scatter to PQ[rp][s][q = pq*32 + b]
            #pragma unroll
            for (int n8 = 0; n8 < 4; n8++)
                #pragma unroll
                for (int ch = 0; ch < 2; ch++) {
                    int f = mi * 16 + g + (ch << 3);
                    if (f < 66) {
                        int b  = n8 * 8 + 2 * t4;        // even
                        int rp = f >> 1, pq = f & 1;
                        int u  = pq * 64 + 2 * b;        // byte offset, 4-aligned
                        uint32_t addr = sb + SM_PQ + (uint32_t)(rp * 2064 + s * 128
                                      + (((u >> 4) ^ (s & 7)) << 4) + (u & 15));
                        sts32(addr, pk2(acc[n8][2 * ch], acc[n8][2 * ch + 1]));
                    }
                }
        }
    }

    // prefetch first rp's B fragments (gmem, independent of PQ barrier)
    uint4 B[8];
    {
        const uint4* p = g_B2f4 + wid * 256 + lane;
        #pragma unroll
        for (int f = 0; f < 8; f++) B[f] = __ldg(p + f * 32);
    }

    __syncthreads();   // PQ complete; x buffer dead -> y staging (fp16)

    // ================= Stage 2: barrier-free, warp owns rp = wid + 8r =================
    #pragma unroll
    for (int r = 0; r < 4; r++) {
        int rp = r * 8 + wid;
        uint4 Bn[8];
        if (r < 3) {                       // prefetch next rp
            const uint4* p = g_B2f4 + (rp + 8) * 256 + lane;
            #pragma unroll
            for (int f = 0; f < 8; f++) Bn[f] = __ldg(p + f * 32);
        } else if (wid == 0) {             // prefetch tail rp = 32
            const uint4* p = g_B2f4 + 32 * 256 + lane;
            #pragma unroll
            for (int f = 0; f < 8; f++) Bn[f] = __ldg(p + f * 32);
        }
        stage2_rp(sb, rp, B, jj, ri, lane);
        #pragma unroll
        for (int f = 0; f < 8; f++) B[f] = Bn[f];
    }
    if (wid == 0) stage2_rp(sb, 32, B, jj, ri, lane);

    __syncthreads();

    // ---- copy-out: fp16 staging -> fp32 gmem (inverts rotation) ----
    #pragma unroll
    for (int i = 0; i < 16; i++) {
        int idx = i * THREADS + tid;            // 0..4095 float4-groups
        int s = idx >> 8, c4 = idx & 255;
        uint32_t M0 = (uint32_t)(c4 * 4);
        uint32_t rot = 4u * (uint32_t)s + ((M0 >> 7) & 3u);
        uint32_t base = sb + SM_XY + (uint32_t)(s * 2048);
        float4 v;
        {
            uint32_t w0 = (M0 & ~31u) | ((M0 + rot) & 31u);
            uint32_t w1 = (M0 & ~31u) | ((M0 + 1 + rot) & 31u);
            uint32_t w2 = (M0 & ~31u) | ((M0 + 2 + rot) & 31u);
            uint32_t w3 = (M0 & ~31u) | ((M0 + 3 + rot) & 31u);
            v.x = __half2float(lds16(base + 2u * w0));
            v.y = __half2float(lds16(base + 2u * w1));
            v.z = __half2float(lds16(base + 2u * w2));
            v.w = __half2float(lds16(base + 2u * w3));
        }
        *reinterpret_cast<float4*>(y + (s_base + s) * 1024 + M0) = v;
    }
}

// ============================================================
// Launch
// ============================================================
extern "C" void kernel_launch(void* const* d_in, const int* in_sizes, int n_in,
                              void* d_out, int out_size) {
    const float* x = (const float*)d_in[0];
    float* y = (float*)d_out;

    build_basis_kernel<<<34, 512>>>();

    cudaFuncSetAttribute(dst_fused_kernel,
                         cudaFuncAttributeMaxDynamicSharedMemorySize, SMEM_TOTAL);
    dst_fused_kernel<<<BATCH / SIGS, THREADS, SMEM_TOTAL>>>(x, y);
}